// round 8
// baseline (speedup 1.0000x reference)
#include <cuda_runtime.h>
#include <cuda_fp16.h>
#include <cstdint>

typedef unsigned long long ull;

#define BB 64
#define FF 4
#define MM 4096
#define DD 1024
#define NITER 15
#define WD 16            // DD/64 sign-bit words (u64)
#define GRID_RUN 128

// ---------------- device scratch ----------------
__device__ ull g_est[2][BB * FF * WD];               // ping-pong estimate bits (1 = negative)
__device__ ull g_in[BB * WD];                        // input bits
__device__ ull g_cbD[FF * MM * WD];                  // codebook bits (cleanup)
__device__ __align__(16) __half g_cb16[(size_t)FF * MM * DD];  // codebook fp16
__device__ __align__(16) __half g_G[(size_t)FF * DD * DD];     // Gram: G[f] = C[f]^T C[f]
__device__ int g_mismatch[NITER];
__device__ int g_bar[NITER];

// ---------------- helpers ----------------
__device__ __forceinline__ uint32_t smem_u32(const void* p) {
    return (uint32_t)__cvta_generic_to_shared(p);
}
__device__ __forceinline__ void ldm_x4_t(uint32_t& r0, uint32_t& r1, uint32_t& r2, uint32_t& r3, uint32_t addr) {
    asm volatile("ldmatrix.sync.aligned.m8n8.x4.trans.shared.b16 {%0,%1,%2,%3}, [%4];\n"
                 : "=r"(r0), "=r"(r1), "=r"(r2), "=r"(r3) : "r"(addr));
}
__device__ __forceinline__ void mma16816(float* c, uint32_t a0, uint32_t a1, uint32_t a2, uint32_t a3,
                                         uint32_t b0, uint32_t b1) {
    asm volatile("mma.sync.aligned.m16n8k16.row.col.f32.f16.f16.f32 "
                 "{%0,%1,%2,%3}, {%4,%5,%6,%7}, {%8,%9}, {%0,%1,%2,%3};\n"
                 : "+f"(c[0]), "+f"(c[1]), "+f"(c[2]), "+f"(c[3])
                 : "r"(a0), "r"(a1), "r"(a2), "r"(a3), "r"(b0), "r"(b1));
}
// 2 sign bits -> packed half2 of +-1 (bit=1 -> -1)
__device__ __forceinline__ uint32_t bexp(uint32_t t) {
    return 0x3C003C00u | ((t & 1u) << 15) | ((t & 2u) << 30);
}
// spread 16 bits to every 4th bit of a u64
__device__ __forceinline__ ull spr4(uint32_t x) {
    ull v = x & 0xFFFFull;
    v = (v | v << 24) & 0x000000FF000000FFull;
    v = (v | v << 12) & 0x000F000F000F000Full;
    v = (v | v << 6)  & 0x0303030303030303ull;
    v = (v | v << 3)  & 0x1111111111111111ull;
    return v;
}

// grid barrier: all GRID_RUN CTAs co-resident
__device__ __forceinline__ void grid_bar(int it) {
    __syncthreads();
    if (threadIdx.x == 0) {
        asm volatile("red.release.gpu.global.add.u32 [%0], %1;"
                     :: "l"(g_bar + it), "r"(1u) : "memory");
        unsigned v;
        do {
            asm volatile("ld.acquire.gpu.global.u32 %0, [%1];"
                         : "=r"(v) : "l"(g_bar + it) : "memory");
        } while (v < GRID_RUN);
    }
    __syncthreads();
}

// ---------------- pack kernels ----------------
__global__ void k_pack_cb(const float* __restrict__ cb) {
    int row  = blockIdx.x * 4 + (threadIdx.x >> 5);
    int lane = threadIdx.x & 31;
    const float* src = cb + (size_t)row * DD;
    __half* dsth = g_cb16 + (size_t)row * DD;
    ull* dstb = g_cbD + row * WD;
    #pragma unroll
    for (int i = 0; i < 8; i++) {
        int d = i * 128 + lane * 4;
        float4 v = *(const float4*)(src + d);
        __half2 h0 = __floats2half2_rn(v.x, v.y);
        __half2 h1 = __floats2half2_rn(v.z, v.w);
        uint2 st;
        st.x = *reinterpret_cast<unsigned*>(&h0);
        st.y = *reinterpret_cast<unsigned*>(&h1);
        *(uint2*)(dsth + d) = st;
        unsigned b0 = __ballot_sync(0xffffffffu, v.x < 0.f);
        unsigned b1 = __ballot_sync(0xffffffffu, v.y < 0.f);
        unsigned b2 = __ballot_sync(0xffffffffu, v.z < 0.f);
        unsigned b3 = __ballot_sync(0xffffffffu, v.w < 0.f);
        if (lane == 0) {
            dstb[i * 2]     = spr4(b0) | (spr4(b1) << 1) | (spr4(b2) << 2) | (spr4(b3) << 3);
            dstb[i * 2 + 1] = spr4(b0 >> 16) | (spr4(b1 >> 16) << 1) | (spr4(b2 >> 16) << 2) | (spr4(b3 >> 16) << 3);
        }
    }
}

__global__ void k_pack_est(const float* __restrict__ inp, const float* __restrict__ est0) {
    int row  = blockIdx.x * 4 + (threadIdx.x >> 5);
    int lane = threadIdx.x & 31;
    if (blockIdx.x == 0 && threadIdx.x < NITER) {
        g_mismatch[threadIdx.x] = 0;
        g_bar[threadIdx.x] = 0;
    }
    const float* src;
    ull* dst;
    if (row < BB * FF) { src = est0 + (size_t)row * DD; dst = g_est[0] + row * WD; }
    else               { int b = row - BB * FF; src = inp + (size_t)b * DD; dst = g_in + b * WD; }
    ull lo = 0;
    #pragma unroll
    for (int i = 0; i < 32; i++) {
        unsigned bal = __ballot_sync(0xffffffffu, src[i * 32 + lane] < 0.f);
        if ((i & 1) == 0) lo = bal;
        else if (lane == 0) dst[i >> 1] = lo | ((ull)bal << 32);
    }
}

// ---------------- Gram matrix: G[f][d][d'] = sum_m C[m,d]*C[m,d'] ----------------
__global__ void k_gram() {
    int f = blockIdx.x / 36, pair = blockIdx.x % 36;
    int i = 0, rem = pair;
    while (rem >= 8 - i) { rem -= 8 - i; i++; }
    int j = i + rem;
    int gi = i << 7, gj = j << 7;
    int t = threadIdx.x, lane = t & 31, w = t >> 5;
    int wm = w >> 1, wn = w & 1;            // warp tile 32m x 64n

    __shared__ __align__(16) __half sI[2][32 * 128];
    __shared__ __align__(16) __half sJ[2][32 * 128];

    const __half* Cf = g_cb16 + (size_t)f * MM * DD;

    float acc[2][8][4];
    #pragma unroll
    for (int a = 0; a < 2; a++)
        #pragma unroll
        for (int b2 = 0; b2 < 8; b2++)
            #pragma unroll
            for (int q = 0; q < 4; q++) acc[a][b2][q] = 0.f;

    uint4 rI[2], rJ[2];
    #pragma unroll
    for (int q = 0; q < 2; q++) {
        int id = t * 2 + q, r = id >> 4, cc = id & 15;
        rI[q] = *(const uint4*)(Cf + (size_t)r * DD + gi + cc * 8);
        rJ[q] = *(const uint4*)(Cf + (size_t)r * DD + gj + cc * 8);
    }
    #pragma unroll
    for (int q = 0; q < 2; q++) {
        int id = t * 2 + q, r = id >> 4, cc = id & 15, sub = cc >> 3, c8 = cc & 7;
        *(uint4*)(&sI[0][sub * 2048 + r * 64 + ((c8 ^ (r & 7)) << 3)]) = rI[q];
        *(uint4*)(&sJ[0][sub * 2048 + r * 64 + ((c8 ^ (r & 7)) << 3)]) = rJ[q];
    }

    for (int c = 0; c < 128; c++) {
        if (c + 1 < 128) {
            int k0 = (c + 1) * 32;
            #pragma unroll
            for (int q = 0; q < 2; q++) {
                int id = t * 2 + q, r = id >> 4, cc = id & 15;
                rI[q] = *(const uint4*)(Cf + (size_t)(k0 + r) * DD + gi + cc * 8);
                rJ[q] = *(const uint4*)(Cf + (size_t)(k0 + r) * DD + gj + cc * 8);
            }
        }
        __syncthreads();
        const __half* bI = sI[c & 1];
        const __half* bJ = sJ[c & 1];
        #pragma unroll
        for (int k16 = 0; k16 < 2; k16++) {
            uint32_t a_[2][4];
            #pragma unroll
            for (int mi = 0; mi < 2; mi++) {
                int col = wm * 32 + mi * 16;
                int sub = col >> 6, cl = col & 63;
                int rr = k16 * 16 + (lane & 15);
                int cc8 = (cl >> 3) + (lane >> 4);
                ldm_x4_t(a_[mi][0], a_[mi][1], a_[mi][2], a_[mi][3],
                         smem_u32(bI + sub * 2048 + rr * 64 + ((cc8 ^ (rr & 7)) << 3)));
            }
            #pragma unroll
            for (int ni = 0; ni < 4; ni++) {
                int col = wn * 64 + ni * 16;
                int sub = col >> 6, cl = col & 63;
                int rr = k16 * 16 + (lane & 15);
                int cc8 = (cl >> 3) + (lane >> 4);
                uint32_t b0, b1, b2, b3;
                ldm_x4_t(b0, b1, b2, b3,
                         smem_u32(bJ + sub * 2048 + rr * 64 + ((cc8 ^ (rr & 7)) << 3)));
                #pragma unroll
                for (int mi = 0; mi < 2; mi++) {
                    mma16816(acc[mi][ni * 2],     a_[mi][0], a_[mi][2], a_[mi][1], a_[mi][3], b0, b1);
                    mma16816(acc[mi][ni * 2 + 1], a_[mi][0], a_[mi][2], a_[mi][1], a_[mi][3], b2, b3);
                }
            }
        }
        if (c + 1 < 128) {
            int buf = (c + 1) & 1;
            #pragma unroll
            for (int q = 0; q < 2; q++) {
                int id = t * 2 + q, r = id >> 4, cc = id & 15, sub = cc >> 3, c8 = cc & 7;
                *(uint4*)(&sI[buf][sub * 2048 + r * 64 + ((c8 ^ (r & 7)) << 3)]) = rI[q];
                *(uint4*)(&sJ[buf][sub * 2048 + r * 64 + ((c8 ^ (r & 7)) << 3)]) = rJ[q];
            }
        }
    }

    __half* Gf = g_G + (size_t)f * DD * DD;
    #pragma unroll
    for (int mi = 0; mi < 2; mi++)
        #pragma unroll
        for (int nf = 0; nf < 8; nf++) {
            int row = gi + wm * 32 + mi * 16 + (lane >> 2);
            int col = gj + wn * 64 + nf * 8 + (lane & 3) * 2;
            float* cc = acc[mi][nf];
            *(__half2*)&Gf[(size_t)row * DD + col]       = __floats2half2_rn(cc[0], cc[1]);
            *(__half2*)&Gf[(size_t)(row + 8) * DD + col] = __floats2half2_rn(cc[2], cc[3]);
            if (i != j) {
                Gf[(size_t)col * DD + row]           = __float2half_rn(cc[0]);
                Gf[(size_t)(col + 1) * DD + row]     = __float2half_rn(cc[1]);
                Gf[(size_t)col * DD + row + 8]       = __float2half_rn(cc[2]);
                Gf[(size_t)(col + 1) * DD + row + 8] = __float2half_rn(cc[3]);
            }
        }
}

// ---------------- persistent kernel: 15 iterations + cleanup ----------------
// grid = 128 CTAs: f = bid>>5, nt = bid&31 (32 d-cols). 512 threads = 16 warps.
// warp = (mg = w&1: 32 m-rows) x (kg = w>>1: 128 k) x 32n.
// B (G) fragments live in REGISTERS across all 15 iterations (64 regs/thread).
// smem: [0,128K) sG during prologue, reused as sCp partials [8][64][33]; bits at +128K.
#define SM_BITS 131072
#define SM_TOT  139264

__global__ void __launch_bounds__(512) k_run(float* __restrict__ out, int out_size) {
    extern __shared__ __align__(16) char smem[];
    __half* sG    = (__half*)smem;                  // prologue only
    float*  sCp   = (float*)smem;                   // partials, reuses sG region
    ull*    sBits = (ull*)(smem + SM_BITS);
    char*   aux   = smem;                           // cleanup scratch

    int t = threadIdx.x, lane = t & 31, w = t >> 5;
    int mg = w & 1, kg = w >> 1;
    int f = blockIdx.x >> 5, nt = blockIdx.x & 31, n0 = nt << 5;

    // prologue: stage G slice (1024k x 32n) swizzled, then ldmatrix B fragments into regs
    {
        const __half* Gf = g_G + (size_t)f * DD * DD + n0;
        for (int idx = t; idx < 4096; idx += 512) {
            int r = idx >> 2, c8 = idx & 3;
            uint4 v = *(const uint4*)(Gf + (size_t)r * DD + c8 * 8);
            *(uint4*)(sG + r * 64 + ((c8 ^ (r & 7)) << 3)) = v;
        }
    }
    __syncthreads();

    int l15 = lane & 15, lh = lane >> 4, lq = lane & 3;
    uint32_t B[8][8];   // [k16 within 128k][2 regs x 4 n8-tiles]
    #pragma unroll
    for (int s = 0; s < 8; s++) {
        int br = kg * 128 + s * 16 + l15;
        int bc8 = lh;
        ldm_x4_t(B[s][0], B[s][1], B[s][2], B[s][3],
                 smem_u32(sG + br * 64 + ((bc8 ^ (br & 7)) << 3)));
        bc8 = 2 + lh;
        ldm_x4_t(B[s][4], B[s][5], B[s][6], B[s][7],
                 smem_u32(sG + br * 64 + ((bc8 ^ (br & 7)) << 3)));
    }
    // safe to reuse sG region: first sCp write is after the bits __syncthreads below,
    // and every warp's ldmatrix precedes that barrier in program order.

    int r0 = mg * 32 + (lane >> 2);

    for (int it = 0; it < NITER; it++) {
        int p = it & 1;
        const ull* E = g_est[p];

        // new_est bits: in ^ (xor of all est) ^ est_f
        for (int idx = t; idx < BB * WD; idx += 512) {
            int b = idx >> 4, wd = idx & 15;
            ull x = g_in[idx];
            x ^= E[(b * FF + 0) * WD + wd] ^ E[(b * FF + 1) * WD + wd]
               ^ E[(b * FF + 2) * WD + wd] ^ E[(b * FF + 3) * WD + wd];
            sBits[idx] = x ^ E[(b * FF + f) * WD + wd];
        }
        __syncthreads();

        float acc[2][4][4];
        #pragma unroll
        for (int mt = 0; mt < 2; mt++)
            #pragma unroll
            for (int n = 0; n < 4; n++)
                #pragma unroll
                for (int q = 0; q < 4; q++) acc[mt][n][q] = 0.f;

        // sync-free, LDSM-free mainloop: A from bits (regs), B resident in regs
        #pragma unroll
        for (int c = 0; c < 2; c++) {
            int C = kg * 2 + c;
            ull w00 = sBits[(r0     ) * WD + C];
            ull w01 = sBits[(r0 +  8) * WD + C];
            ull w10 = sBits[(r0 + 16) * WD + C];
            ull w11 = sBits[(r0 + 24) * WD + C];
            #pragma unroll
            for (int s4 = 0; s4 < 4; s4++) {
                int s = c * 4 + s4;
                int sh = s4 * 16 + lq * 2;
                uint32_t t00 = (uint32_t)(w00 >> sh), t01 = (uint32_t)(w01 >> sh);
                uint32_t t10 = (uint32_t)(w10 >> sh), t11 = (uint32_t)(w11 >> sh);
                uint32_t a00 = bexp(t00), a01 = bexp(t01);
                uint32_t a02 = bexp(t00 >> 8), a03 = bexp(t01 >> 8);
                uint32_t a10 = bexp(t10), a11 = bexp(t11);
                uint32_t a12 = bexp(t10 >> 8), a13 = bexp(t11 >> 8);
                #pragma unroll
                for (int n = 0; n < 4; n++) {
                    mma16816(acc[0][n], a00, a01, a02, a03, B[s][n * 2], B[s][n * 2 + 1]);
                    mma16816(acc[1][n], a10, a11, a12, a13, B[s][n * 2], B[s][n * 2 + 1]);
                }
            }
        }

        // stage K-partials: sCp[kg][64][33]
        #pragma unroll
        for (int mt = 0; mt < 2; mt++) {
            int rr = mg * 32 + mt * 16 + (lane >> 2);
            #pragma unroll
            for (int n = 0; n < 4; n++) {
                float* P = sCp + (kg * 64 + rr) * 33 + n * 8 + lq * 2;
                P[0]          = acc[mt][n][0];
                P[1]          = acc[mt][n][1];
                P[33 * 8]     = acc[mt][n][2];
                P[33 * 8 + 1] = acc[mt][n][3];
            }
        }
        __syncthreads();

        // reduce 8 K-partials, sign (sign(0)=+1 -> strict <0), ballot-pack, compare
        {
            int cnt = 0;
            #pragma unroll
            for (int rr4 = 0; rr4 < 4; rr4++) {
                int row = w * 4 + rr4;
                float s = 0.f;
                #pragma unroll
                for (int kgi = 0; kgi < 8; kgi++)
                    s += sCp[(kgi * 64 + row) * 33 + lane];
                unsigned bal = __ballot_sync(0xffffffffu, s < 0.f);
                if (lane == rr4) {
                    int ei = (row * FF + f) * 32 + nt;
                    uint32_t old = ((const uint32_t*)g_est[p])[ei];
                    ((uint32_t*)g_est[p ^ 1])[ei] = bal;
                    if (bal != old) cnt = 1;
                }
            }
            unsigned msk = __ballot_sync(0xffffffffu, cnt != 0);
            if (lane == 0 && msk) atomicAdd(&g_mismatch[it], __popc(msk));
        }

        grid_bar(it);
    }

    // ---------------- cleanup: argmax|sim| per (b, f), est floats, iters/conv ----------------
    {
        int f2 = blockIdx.x >> 5, bg = blockIdx.x & 31;   // 2 batches per CTA
        ull* sE = (ull*)aux;                              // 2 x 16 ull
        int* rA = (int*)(aux + 256);
        int* rI = (int*)(aux + 256 + 2048);
        const ull* Ef = g_est[NITER & 1];

        if (t < 32) {
            int j = t >> 4, wd = t & 15;
            sE[j * WD + wd] = Ef[(size_t)((bg * 2 + j) * FF + f2) * WD + wd];
        }
        __syncthreads();

        const ull* cb = g_cbD + (size_t)f2 * MM * WD;
        int bestA[2] = {-1, -1}, bestI[2] = {0, 0};
        for (int m = t; m < MM; m += 512) {
            ull rb[WD];
            const ull* rp = cb + (size_t)m * WD;
            #pragma unroll
            for (int q = 0; q < WD; q++) rb[q] = rp[q];
            #pragma unroll
            for (int j = 0; j < 2; j++) {
                int h = 0;
                #pragma unroll
                for (int q = 0; q < WD; q++) h += __popcll(rb[q] ^ sE[j * WD + q]);
                int s = DD - 2 * h;
                int a = s < 0 ? -s : s;
                if (a > bestA[j]) { bestA[j] = a; bestI[j] = m; }
            }
        }

        #pragma unroll
        for (int j = 0; j < 2; j++) {
            __syncthreads();
            rA[t] = bestA[j]; rI[t] = bestI[j];
            __syncthreads();
            for (int off = 256; off; off >>= 1) {
                if (t < off) {
                    int a2 = rA[t + off], i2 = rI[t + off];
                    if (a2 > rA[t] || (a2 == rA[t] && i2 < rI[t])) { rA[t] = a2; rI[t] = i2; }
                }
                __syncthreads();
            }
            int idx = (bg * 2 + j) * FF + f2;
            if (t == 0 && idx < out_size) out[idx] = (float)rI[0];
            if (out_size >= 256 + BB * FF * DD) {
                float* oe = out + 256 + (size_t)idx * DD;
                for (int d = t; d < DD; d += 512) {
                    int bit = (int)((sE[j * WD + (d >> 6)] >> (d & 63)) & 1ULL);
                    oe[d] = bit ? -1.f : 1.f;
                }
            }
        }

        if (blockIdx.x == 0 && t == 0 && out_size >= 256 + BB * FF * DD + 2) {
            int iters = NITER, conv = 0;
            for (int tt = 0; tt < NITER; tt++)
                if (g_mismatch[tt] == 0) { iters = tt + 1; conv = 1; break; }
            out[256 + BB * FF * DD]     = (float)iters;
            out[256 + BB * FF * DD + 1] = (float)conv;
        }
    }
}

// ---------------- launch ----------------
extern "C" void kernel_launch(void* const* d_in, const int* in_sizes, int n_in,
                              void* d_out, int out_size) {
    const float* input = nullptr;
    const float* est0  = nullptr;
    const float* cb    = nullptr;
    for (int i = 0; i < n_in; i++) {
        if (in_sizes[i] == BB * DD)            input = (const float*)d_in[i];
        else if (in_sizes[i] == BB * FF * DD)  est0  = (const float*)d_in[i];
        else if (in_sizes[i] == FF * MM * DD)  cb    = (const float*)d_in[i];
    }
    cudaFuncSetAttribute(k_run, cudaFuncAttributeMaxDynamicSharedMemorySize, SM_TOT);
    k_pack_est<<<80, 128>>>(input, est0);
    k_pack_cb<<<FF * MM / 4, 128>>>(cb);
    k_gram<<<FF * 36, 256>>>();
    k_run<<<GRID_RUN, 512, SM_TOT>>>((float*)d_out, out_size);
}